// round 6
// baseline (speedup 1.0000x reference)
#include <cuda_runtime.h>

// 9x9 zero-padded box filter, 128 independent 512x512 fp32 images.
// Full-width row pipeline: CTA = 512-wide x TH-row band.
// Vertical 9-sum slides in registers (new row from DRAM, old row from L2),
// horizontal 9-sum via one smem float4 store + 2 neighbor float4 loads.
// R6: TH=32, 2-row barrier groups, occupancy forced to 8 CTAs/SM.

#define W   512
#define H   512
#define TH  32                  // rows per CTA band
#define NT  128                 // one thread per float4 column group (512/4)
#define W4  (W / 4)             // 128
#define SLW 130                 // smem slot width in float4 (128 + 2 halo)

__global__ __launch_bounds__(NT, 8)
void box9_kernel(const float* __restrict__ xin, float* __restrict__ outp) {
    // 4 row-slots: 2 rows in flight per barrier, alternating pairs.
    __shared__ __align__(16) float4 buf[4][SLW];

    const int t  = threadIdx.x;
    const int y0 = blockIdx.x * TH;
    const size_t imgoff = (size_t)blockIdx.y * (W * H);
    const float4* __restrict__ base  = reinterpret_cast<const float4*>(xin + imgoff);
    float4* __restrict__       obase = reinterpret_cast<float4*>(outp + imgoff);

    const float4 z4 = make_float4(0.f, 0.f, 0.f, 0.f);
    if (t < 4) {
        buf[t][0]       = z4;
        buf[t][SLW - 1] = z4;
    }

    // ---- prologue: vs = sum of input rows [y0-5, y0+3] (zeros outside) ----
    // Invariant before the slide at output row y: vs = sum rows [y-5, y+3].
    float4 vs = z4;
    #pragma unroll
    for (int i = -5; i <= 3; i++) {
        int r = y0 + i;
        if ((unsigned)r < (unsigned)H) {
            float4 v = base[r * W4 + t];
            vs.x += v.x; vs.y += v.y; vs.z += v.z; vs.w += v.w;
        }
    }

    // prefetch rows for the first iteration (output rows y0, y0+1):
    //   n = x[y+4], o = x[y-5]
    float4 n0 = z4, o0 = z4, n1 = z4, o1 = z4;
    { int r;
      r = y0 + 4; if ((unsigned)r < (unsigned)H) n0 = base[r * W4 + t];
      r = y0 - 5; if ((unsigned)r < (unsigned)H) o0 = base[r * W4 + t];
      r = y0 + 5; if ((unsigned)r < (unsigned)H) n1 = base[r * W4 + t];
      r = y0 - 4; if ((unsigned)r < (unsigned)H) o1 = base[r * W4 + t];
    }

    #pragma unroll 2
    for (int k = 0; k < TH / 2; k++) {
        const int y = y0 + 2 * k;
        float4 na = n0, oa = o0, nb = n1, ob = o1;

        // prefetch rows for next iteration (output rows y+2, y+3)
        if (k + 1 < TH / 2) {
            int r;
            n0 = z4; o0 = z4; n1 = z4; o1 = z4;
            r = y + 6; if ((unsigned)r < (unsigned)H) n0 = base[r * W4 + t];
            r = y - 3; if ((unsigned)r < (unsigned)H) o0 = base[r * W4 + t];
            r = y + 7; if ((unsigned)r < (unsigned)H) n1 = base[r * W4 + t];
            r = y - 2; if ((unsigned)r < (unsigned)H) o1 = base[r * W4 + t];
        }

        // vertical slide, two rows
        vs.x += na.x - oa.x; vs.y += na.y - oa.y;
        vs.z += na.z - oa.z; vs.w += na.w - oa.w;
        float4 vs0 = vs;
        buf[(2 * k) & 3][t + 1] = vs0;

        vs.x += nb.x - ob.x; vs.y += nb.y - ob.y;
        vs.z += nb.z - ob.z; vs.w += nb.w - ob.w;
        float4 vs1 = vs;
        buf[(2 * k + 1) & 3][t + 1] = vs1;

        __syncthreads();

        // horizontal slide, row y
        {
            float4 a = buf[(2 * k) & 3][t];
            float4 c = buf[(2 * k) & 3][t + 2];
            float sb = (vs0.x + vs0.y) + (vs0.z + vs0.w);
            float sa = (a.x + a.y) + (a.z + a.w);
            float h0 = sa + sb + c.x;
            float h1 = h0 - a.x + c.y;
            float h2 = h1 - a.y + c.z;
            float h3 = h2 - a.z + c.w;
            obase[y * W4 + t] = make_float4(h0, h1, h2, h3);
        }
        // horizontal slide, row y+1
        {
            float4 a = buf[(2 * k + 1) & 3][t];
            float4 c = buf[(2 * k + 1) & 3][t + 2];
            float sb = (vs1.x + vs1.y) + (vs1.z + vs1.w);
            float sa = (a.x + a.y) + (a.z + a.w);
            float h0 = sa + sb + c.x;
            float h1 = h0 - a.x + c.y;
            float h2 = h1 - a.y + c.z;
            float h3 = h2 - a.z + c.w;
            obase[(y + 1) * W4 + t] = make_float4(h0, h1, h2, h3);
        }
    }
}

extern "C" void kernel_launch(void* const* d_in, const int* in_sizes, int n_in,
                              void* d_out, int out_size) {
    const float* x = (const float*)d_in[0];
    float* out = (float*)d_out;
    int nimg = in_sizes[0] / (W * H);     // 128
    dim3 grid(H / TH, nimg);              // (16, 128) = 2048 CTAs
    box9_kernel<<<grid, NT>>>(x, out);
}

// round 7
// speedup vs baseline: 1.2012x; 1.2012x over previous
#include <cuda_runtime.h>

// 9x9 zero-padded box filter, 128 independent 512x512 fp32 images.
// Full-width row pipeline: CTA = 512-wide x TH-row band (R3 structure,
// the measured minimum-traffic config). Vertical 9-sum slides in registers
// (new row from DRAM, old row from L2), horizontal 9-sum via one smem
// float4 store + 2 neighbor float4 loads.
// R7: streaming stores (__stcs) so the output stream doesn't evict the
// input working set from L2.

#define W   512
#define H   512
#define TH  64                  // rows per CTA band
#define NT  128                 // one thread per float4 column group (512/4)
#define W4  (W / 4)             // 128

__global__ __launch_bounds__(NT) void box9_kernel(const float* __restrict__ xin,
                                                  float* __restrict__ outp) {
    // 4 row-buffers (2 rows in flight per barrier, alternating pairs).
    // Slot s: index t+1 is own column group; 0 and 129 are the zero halo.
    __shared__ __align__(16) float4 buf[4][132];

    const int t  = threadIdx.x;
    const int y0 = blockIdx.x * TH;
    const size_t imgoff = (size_t)blockIdx.y * (W * H);
    const float4* __restrict__ base  = reinterpret_cast<const float4*>(xin + imgoff);
    float4* __restrict__       obase = reinterpret_cast<float4*>(outp + imgoff);

    const float4 z4 = make_float4(0.f, 0.f, 0.f, 0.f);
    if (t < 4) {
        buf[t][0]   = z4;
        buf[t][129] = z4;
    }

    // ---- prologue: vs = sum of input rows [y0-5, y0+3] (zeros outside) ----
    // Invariant before the slide at output row y: vs = sum rows [y-5, y+3].
    float4 vs = z4;
    #pragma unroll
    for (int i = -5; i <= 3; i++) {
        int r = y0 + i;
        if ((unsigned)r < (unsigned)H) {
            float4 v = base[r * W4 + t];
            vs.x += v.x; vs.y += v.y; vs.z += v.z; vs.w += v.w;
        }
    }

    // prefetch rows for the first iteration (output rows y0, y0+1):
    //   n = x[y+4], o = x[y-5]
    float4 n0 = z4, o0 = z4, n1 = z4, o1 = z4;
    { int r;
      r = y0 + 4; if ((unsigned)r < (unsigned)H) n0 = base[r * W4 + t];
      r = y0 - 5; if ((unsigned)r < (unsigned)H) o0 = base[r * W4 + t];
      r = y0 + 5; if ((unsigned)r < (unsigned)H) n1 = base[r * W4 + t];
      r = y0 - 4; if ((unsigned)r < (unsigned)H) o1 = base[r * W4 + t];
    }

    #pragma unroll 2
    for (int k = 0; k < TH / 2; k++) {
        const int y = y0 + 2 * k;
        float4 na = n0, oa = o0, nb = n1, ob = o1;

        // prefetch rows for next iteration (output rows y+2, y+3)
        if (k + 1 < TH / 2) {
            int r;
            n0 = z4; o0 = z4; n1 = z4; o1 = z4;
            r = y + 6; if ((unsigned)r < (unsigned)H) n0 = base[r * W4 + t];
            r = y - 3; if ((unsigned)r < (unsigned)H) o0 = base[r * W4 + t];
            r = y + 7; if ((unsigned)r < (unsigned)H) n1 = base[r * W4 + t];
            r = y - 2; if ((unsigned)r < (unsigned)H) o1 = base[r * W4 + t];
        }

        // vertical slide, two rows
        vs.x += na.x - oa.x; vs.y += na.y - oa.y;
        vs.z += na.z - oa.z; vs.w += na.w - oa.w;
        float4 vs0 = vs;
        buf[(2 * k) & 3][t + 1] = vs0;

        vs.x += nb.x - ob.x; vs.y += nb.y - ob.y;
        vs.z += nb.z - ob.z; vs.w += nb.w - ob.w;
        float4 vs1 = vs;
        buf[(2 * k + 1) & 3][t + 1] = vs1;

        __syncthreads();

        // horizontal slide, row y (streaming store: keep L2 for input)
        {
            float4 a = buf[(2 * k) & 3][t];
            float4 c = buf[(2 * k) & 3][t + 2];
            float sb = (vs0.x + vs0.y) + (vs0.z + vs0.w);
            float sa = (a.x + a.y) + (a.z + a.w);
            float h0 = sa + sb + c.x;
            float h1 = h0 - a.x + c.y;
            float h2 = h1 - a.y + c.z;
            float h3 = h2 - a.z + c.w;
            __stcs(&obase[y * W4 + t], make_float4(h0, h1, h2, h3));
        }
        // horizontal slide, row y+1
        {
            float4 a = buf[(2 * k + 1) & 3][t];
            float4 c = buf[(2 * k + 1) & 3][t + 2];
            float sb = (vs1.x + vs1.y) + (vs1.z + vs1.w);
            float sa = (a.x + a.y) + (a.z + a.w);
            float h0 = sa + sb + c.x;
            float h1 = h0 - a.x + c.y;
            float h2 = h1 - a.y + c.z;
            float h3 = h2 - a.z + c.w;
            __stcs(&obase[(y + 1) * W4 + t], make_float4(h0, h1, h2, h3));
        }
    }
}

extern "C" void kernel_launch(void* const* d_in, const int* in_sizes, int n_in,
                              void* d_out, int out_size) {
    const float* x = (const float*)d_in[0];
    float* out = (float*)d_out;
    int nimg = in_sizes[0] / (W * H);     // 128
    dim3 grid(H / TH, nimg);              // (8, 128) = 1024 CTAs
    box9_kernel<<<grid, NT>>>(x, out);
}